// round 9
// baseline (speedup 1.0000x reference)
#include <cuda_runtime.h>
#include <cuda_bf16.h>
#include <cstdint>

// Problem constants
constexpr int NB  = 16;    // batch
constexpr int LQ  = 256;
constexpr int LK  = 256;
constexpr int H   = 256;   // hidden = DQ = DK = DV

// Scratch (no cudaMalloc allowed)
__device__ float g_q[NB * LQ * H];
__device__ float g_k[NB * LK * H];
__device__ float g_s[NB * LQ * LK];   // raw scores

__device__ __forceinline__ float tanha(float x) {
    float r;
    asm("tanh.approx.f32 %0, %1;" : "=f"(r) : "f"(x));
    return r;
}

__device__ __forceinline__ uint32_t smem_u32(const void* p) {
    uint32_t a;
    asm("{ .reg .u64 t; cvta.to.shared.u64 t, %1; cvt.u32.u64 %0, t; }"
        : "=r"(a) : "l"(p));
    return a;
}

__device__ __forceinline__ void ldsm_x4(uint32_t* r, uint32_t addr) {
    asm volatile("ldmatrix.sync.aligned.m8n8.x4.shared.b16 {%0,%1,%2,%3}, [%4];"
        : "=r"(r[0]), "=r"(r[1]), "=r"(r[2]), "=r"(r[3]) : "r"(addr));
}
__device__ __forceinline__ void ldsm_x2(uint32_t* r, uint32_t addr) {
    asm volatile("ldmatrix.sync.aligned.m8n8.x2.shared.b16 {%0,%1}, [%2];"
        : "=r"(r[0]), "=r"(r[1]) : "r"(addr));
}
__device__ __forceinline__ void mma_bf16(float* c, const uint32_t* a, const uint32_t* b) {
    asm volatile(
        "mma.sync.aligned.m16n8k16.row.col.f32.bf16.bf16.f32 "
        "{%0,%1,%2,%3}, {%4,%5,%6,%7}, {%8,%9}, {%0,%1,%2,%3};"
        : "+f"(c[0]), "+f"(c[1]), "+f"(c[2]), "+f"(c[3])
        : "r"(a[0]), "r"(a[1]), "r"(a[2]), "r"(a[3]), "r"(b[0]), "r"(b[1]));
}

__device__ __forceinline__ uint32_t pack_hi(float x, float y) {
    __nv_bfloat162 v;
    v.x = __float2bfloat16(x);
    v.y = __float2bfloat16(y);
    return *(uint32_t*)&v;
}
__device__ __forceinline__ uint32_t pack_lo(float x, float y) {
    __nv_bfloat16 hx = __float2bfloat16(x);
    __nv_bfloat16 hy = __float2bfloat16(y);
    __nv_bfloat162 v;
    v.x = __float2bfloat16(x - __bfloat162float(hx));
    v.y = __float2bfloat16(y - __bfloat162float(hy));
    return *(uint32_t*)&v;
}

// ===========================================================================
// Kernel 1: tensor-core projections via mma.sync bf16x3 split (fused convert)
//   C ≈ Ah·Wh + Al·Wh + Ah·Wl  (fp32 accumulate; dropped Al·Wl ~ 4e-6)
// CTA: 64x64 tile, BK=32, 256 threads (8 warps 4x2, warp tile 16x32).
// 512 CTAs -> ~3.5 CTAs/SM: staging latency overlaps across CTAs.
// ===========================================================================
__global__ __launch_bounds__(256) void proj_mma_kernel(
    const float* __restrict__ Aq, const float* __restrict__ Ak,
    const float* __restrict__ Wq, const float* __restrict__ Wk,
    const int* __restrict__ valid_lens)
{
    constexpr int BM = 64, BN = 64, BK = 32, BKP = 40;   // padded k-stride
    __shared__ __nv_bfloat16 sAh[BM][BKP], sAl[BM][BKP];
    __shared__ __nv_bfloat16 sBh[BN][BKP], sBl[BN][BKP];

    const int z  = blockIdx.z;            // 0: q-proj, 1: k-proj
    const int m0 = blockIdx.x * BM;
    const int n0 = blockIdx.y * BN;

    // k-projection rows beyond valid_len are never read by score_kernel
    if (z) {
        const int b = m0 >> 8;
        if ((m0 & 255) >= __ldg(&valid_lens[b])) return;
    }

    const float* A = z ? Ak : Aq;
    const float* W = z ? Wk : Wq;
    float*       C = z ? g_k : g_q;

    const int t    = threadIdx.x;
    const int lane = t & 31;
    const int warp = t >> 5;
    const int wm   = (warp & 3) * 16;     // warp m offset (4 warps cover 64)
    const int wn   = (warp >> 2) * 32;    // warp n offset (2 warps cover 64)

    float acc[4][4] = {};                 // [nt][frag], warp tile 16x32

    for (int k0 = 0; k0 < H; k0 += BK) {
        // --- stage A (64 x 32 fp32 -> hi/lo bf16): 512 float4, 2/thread ---
        #pragma unroll
        for (int i = 0; i < 2; i++) {
            const int idx = t + i * 256;
            const int r   = idx >> 3;          // 8 float4 per row
            const int c   = (idx & 7) << 2;
            float4 v = *(const float4*)&A[(m0 + r) * H + k0 + c];
            *(uint32_t*)&sAh[r][c]     = pack_hi(v.x, v.y);
            *(uint32_t*)&sAh[r][c + 2] = pack_hi(v.z, v.w);
            *(uint32_t*)&sAl[r][c]     = pack_lo(v.x, v.y);
            *(uint32_t*)&sAl[r][c + 2] = pack_lo(v.z, v.w);
        }
        // --- stage B transposed: sB[n][k] = W[k0+k][n0+n], 512 float4 ---
        #pragma unroll
        for (int i = 0; i < 2; i++) {
            const int idx = t + i * 256;
            const int kr  = idx >> 4;          // 16 float4 per W row
            const int nc  = (idx & 15) << 2;
            float4 v = *(const float4*)&W[(k0 + kr) * H + n0 + nc];
            float vf[4] = {v.x, v.y, v.z, v.w};
            #pragma unroll
            for (int e = 0; e < 4; e++) {
                __nv_bfloat16 h = __float2bfloat16(vf[e]);
                sBh[nc + e][kr] = h;
                sBl[nc + e][kr] = __float2bfloat16(vf[e] - __bfloat162float(h));
            }
        }
        __syncthreads();

        #pragma unroll
        for (int ks = 0; ks < 2; ks++) {
            const int kb = ks * 16;

            uint32_t ah[4], al[4];
            {
                const int row = wm + (lane & 15);
                const int kc  = kb + ((lane >> 4) << 3);
                ldsm_x4(ah, smem_u32(&sAh[row][kc]));
                ldsm_x4(al, smem_u32(&sAl[row][kc]));
            }
            #pragma unroll
            for (int nt = 0; nt < 4; nt++) {
                uint32_t bh[2], bl[2];
                const int row = wn + nt * 8 + (lane & 7);
                const int kc  = kb + (((lane >> 3) & 1) << 3);
                ldsm_x2(bh, smem_u32(&sBh[row][kc]));
                ldsm_x2(bl, smem_u32(&sBl[row][kc]));
                mma_bf16(acc[nt], ah, bh);
                mma_bf16(acc[nt], al, bh);
                mma_bf16(acc[nt], ah, bl);
            }
        }
        __syncthreads();
    }

    // --- epilogue: fragment -> gmem ---
    {
        const int r0 = m0 + wm + (lane >> 2);
        #pragma unroll
        for (int nt = 0; nt < 4; nt++) {
            const int c0 = n0 + wn + nt * 8 + (lane & 3) * 2;
            *(float2*)&C[r0 * H + c0]       = make_float2(acc[nt][0], acc[nt][1]);
            *(float2*)&C[(r0 + 8) * H + c0] = make_float2(acc[nt][2], acc[nt][3]);
        }
    }
}

// ---------------------------------------------------------------------------
// Kernel 2: scores[b, q0:q0+16, j0:j0+32] = sum_h w[h]*tanh(q+k)
// One CTA per (j-tile, b, q-tile); CTAs beyond valid_len exit instantly.
// ---------------------------------------------------------------------------
__global__ __launch_bounds__(128, 4) void score_kernel(
    const int* __restrict__ valid_lens, const float* __restrict__ w_v)
{
    constexpr int QI = 16;
    constexpr int KJ = 32;
    constexpr int HP = H + 4;

    const int jt = blockIdx.x;
    const int b  = blockIdx.y;
    const int q0 = blockIdx.z * QI;
    const int j0 = jt * KJ;

    const int vl = __ldg(&valid_lens[b]);
    if (j0 >= vl) return;

    extern __shared__ float sm[];
    float* sq = sm;             // QI * HP
    float* sk = sq + QI * HP;   // KJ * HP
    float* sw = sk + KJ * HP;   // H

    const int t    = threadIdx.x;
    const int lane = t & 31;
    const int warp = t >> 5;

    for (int idx = t; idx < QI * (H / 4); idx += 128) {
        const int i  = idx >> 6;
        const int hc = (idx & 63) << 2;
        *(float4*)&sq[i * HP + hc] =
            *(const float4*)&g_q[(b * LQ + q0 + i) * H + hc];
    }
    for (int idx = t; idx < KJ * (H / 4); idx += 128) {
        const int j  = idx >> 6;
        const int hc = (idx & 63) << 2;
        *(float4*)&sk[j * HP + hc] =
            *(const float4*)&g_k[(b * LK + j0 + j) * H + hc];
    }
    if (t < H / 4) *(float4*)&sw[t * 4] = *(const float4*)&w_v[t * 4];
    __syncthreads();

    float a0 = 0.f, a1 = 0.f, a2 = 0.f, a3 = 0.f;
    const float* qp0 = &sq[(warp * 4 + 0) * HP];
    const float* qp1 = &sq[(warp * 4 + 1) * HP];
    const float* qp2 = &sq[(warp * 4 + 2) * HP];
    const float* qp3 = &sq[(warp * 4 + 3) * HP];
    const float* kp  = &sk[lane * HP];

    #pragma unroll 2
    for (int h = 0; h < H; h += 4) {
        float4 k4 = *(const float4*)&kp[h];
        float4 w4 = *(const float4*)&sw[h];
        float4 q0v = *(const float4*)&qp0[h];
        float4 q1v = *(const float4*)&qp1[h];
        float4 q2v = *(const float4*)&qp2[h];
        float4 q3v = *(const float4*)&qp3[h];

        a0 += w4.x * tanha(q0v.x + k4.x);
        a0 += w4.y * tanha(q0v.y + k4.y);
        a0 += w4.z * tanha(q0v.z + k4.z);
        a0 += w4.w * tanha(q0v.w + k4.w);

        a1 += w4.x * tanha(q1v.x + k4.x);
        a1 += w4.y * tanha(q1v.y + k4.y);
        a1 += w4.z * tanha(q1v.z + k4.z);
        a1 += w4.w * tanha(q1v.w + k4.w);

        a2 += w4.x * tanha(q2v.x + k4.x);
        a2 += w4.y * tanha(q2v.y + k4.y);
        a2 += w4.z * tanha(q2v.z + k4.z);
        a2 += w4.w * tanha(q2v.w + k4.w);

        a3 += w4.x * tanha(q3v.x + k4.x);
        a3 += w4.y * tanha(q3v.y + k4.y);
        a3 += w4.z * tanha(q3v.z + k4.z);
        a3 += w4.w * tanha(q3v.w + k4.w);
    }

    const int rbase = b * LQ + q0 + warp * 4;
    g_s[(rbase + 0) * LK + j0 + lane] = a0;
    g_s[(rbase + 1) * LK + j0 + lane] = a1;
    g_s[(rbase + 2) * LK + j0 + lane] = a2;
    g_s[(rbase + 3) * LK + j0 + lane] = a3;
}

// ---------------------------------------------------------------------------
// Kernel 3: masked softmax over j + out = P @ V
// Stages only columns j < valid_len; exp pass zeroes the rest of smem.
// ---------------------------------------------------------------------------
__global__ __launch_bounds__(128) void softpv_kernel(
    const float* __restrict__ values, const int* __restrict__ valid_lens,
    float* __restrict__ out)
{
    constexpr int QI = 8;
    __shared__ float sp[QI * LK];

    const int b    = blockIdx.x;
    const int q0   = blockIdx.y * QI;
    const int t    = threadIdx.x;
    const int lane = t & 31;
    const int warp = t >> 5;

    const int vl = valid_lens[b];

    for (int idx = t; idx < QI * (LK / 4); idx += 128) {
        const int i  = idx >> 6;
        const int jc = (idx & 63) << 2;
        if (jc < vl)
            *(float4*)&sp[i * LK + jc] =
                *(const float4*)&g_s[(b * LQ + q0 + i) * LK + jc];
    }
    __syncthreads();

    #pragma unroll
    for (int rr = 0; rr < 2; rr++) {
        const int r = warp + rr * 4;
        float* row = &sp[r * LK];

        float m = -1e30f;
        for (int j = lane; j < LK; j += 32) {
            float s = (j < vl) ? row[j] : -1e30f;
            m = fmaxf(m, s);
        }
        #pragma unroll
        for (int o = 16; o; o >>= 1) m = fmaxf(m, __shfl_xor_sync(0xffffffffu, m, o));

        float ssum = 0.f;
        for (int j = lane; j < LK; j += 32) {
            float e = (j < vl) ? __expf(row[j] - m) : 0.f;
            row[j] = e;
            ssum += e;
        }
        #pragma unroll
        for (int o = 16; o; o >>= 1) ssum += __shfl_xor_sync(0xffffffffu, ssum, o);

        const float inv = 1.0f / ssum;
        for (int j = lane; j < LK; j += 32) row[j] *= inv;
    }
    __syncthreads();

    const int ig = (t >> 6) * 4;        // 0 or 4
    const int v0 = (t & 63) * 4;        // 0..252
    float acc[4][4] = {};
    const float* vb = &values[b * LK * H];

    const int jend = min(LK, (vl + 3) & ~3);
    for (int j = 0; j < jend; j += 4) {
        float vvf[4][4];
        #pragma unroll
        for (int jj = 0; jj < 4; jj++) {
            float4 tmp = *(const float4*)&vb[(j + jj) * H + v0];
            vvf[jj][0] = tmp.x; vvf[jj][1] = tmp.y; vvf[jj][2] = tmp.z; vvf[jj][3] = tmp.w;
        }
        #pragma unroll
        for (int r = 0; r < 4; r++) {
            float4 p = *(const float4*)&sp[(ig + r) * LK + j];
            #pragma unroll
            for (int c = 0; c < 4; c++) {
                acc[r][c] += p.x * vvf[0][c];
                acc[r][c] += p.y * vvf[1][c];
                acc[r][c] += p.z * vvf[2][c];
                acc[r][c] += p.w * vvf[3][c];
            }
        }
    }

    #pragma unroll
    for (int r = 0; r < 4; r++) {
        float4 o = make_float4(acc[r][0], acc[r][1], acc[r][2], acc[r][3]);
        *(float4*)&out[(b * LQ + q0 + ig + r) * H + v0] = o;
    }
}

// ---------------------------------------------------------------------------
extern "C" void kernel_launch(void* const* d_in, const int* in_sizes, int n_in,
                              void* d_out, int out_size) {
    (void)in_sizes; (void)n_in; (void)out_size;
    const float* queries = (const float*)d_in[0];
    const float* keys    = (const float*)d_in[1];
    const float* values  = (const float*)d_in[2];
    const int*   vlens   = (const int*)d_in[3];
    const float* Wq      = (const float*)d_in[4];
    const float* Wk      = (const float*)d_in[5];
    const float* wv      = (const float*)d_in[6];
    float* out = (float*)d_out;

    dim3 pg((NB * LQ) / 64, H / 64, 2);   // 64 x 4 x 2 = 512 CTAs
    proj_mma_kernel<<<pg, 256>>>(queries, keys, Wq, Wk, vlens);

    constexpr int QI = 16, KJ = 32, HP = H + 4;
    constexpr int SMEM = (QI * HP + KJ * HP + H) * (int)sizeof(float);
    cudaFuncSetAttribute(score_kernel, cudaFuncAttributeMaxDynamicSharedMemorySize, SMEM);
    dim3 sg(LK / KJ, NB, LQ / QI);   // j-tile fastest
    score_kernel<<<sg, 128, SMEM>>>(vlens, wv);

    dim3 og(NB, LQ / 8);
    softpv_kernel<<<og, 128>>>(values, vlens, out);
}

// round 10
// speedup vs baseline: 1.1233x; 1.1233x over previous
#include <cuda_runtime.h>
#include <cuda_bf16.h>
#include <cstdint>

// Problem constants
constexpr int NB  = 16;    // batch
constexpr int LQ  = 256;
constexpr int LK  = 256;
constexpr int H   = 256;   // hidden = DQ = DK = DV

// Scratch (no cudaMalloc allowed)
__device__ float g_q[NB * LQ * H];
__device__ float g_k[NB * LK * H];
__device__ float g_s[NB * LQ * LK];   // raw scores

__device__ __forceinline__ float tanha(float x) {
    float r;
    asm("tanh.approx.f32 %0, %1;" : "=f"(r) : "f"(x));
    return r;
}

__device__ __forceinline__ uint32_t smem_u32(const void* p) {
    uint32_t a;
    asm("{ .reg .u64 t; cvta.to.shared.u64 t, %1; cvt.u32.u64 %0, t; }"
        : "=r"(a) : "l"(p));
    return a;
}

__device__ __forceinline__ void ldsm_x4(uint32_t* r, uint32_t addr) {
    asm volatile("ldmatrix.sync.aligned.m8n8.x4.shared.b16 {%0,%1,%2,%3}, [%4];"
        : "=r"(r[0]), "=r"(r[1]), "=r"(r[2]), "=r"(r[3]) : "r"(addr));
}
__device__ __forceinline__ void ldsm_x2_trans(uint32_t* r, uint32_t addr) {
    asm volatile("ldmatrix.sync.aligned.m8n8.x2.trans.shared.b16 {%0,%1}, [%2];"
        : "=r"(r[0]), "=r"(r[1]) : "r"(addr));
}
__device__ __forceinline__ void mma_bf16(float* c, const uint32_t* a, const uint32_t* b) {
    asm volatile(
        "mma.sync.aligned.m16n8k16.row.col.f32.bf16.bf16.f32 "
        "{%0,%1,%2,%3}, {%4,%5,%6,%7}, {%8,%9}, {%0,%1,%2,%3};"
        : "+f"(c[0]), "+f"(c[1]), "+f"(c[2]), "+f"(c[3])
        : "r"(a[0]), "r"(a[1]), "r"(a[2]), "r"(a[3]), "r"(b[0]), "r"(b[1]));
}

__device__ __forceinline__ uint32_t pack_hi(float x, float y) {
    __nv_bfloat162 v;
    v.x = __float2bfloat16(x);
    v.y = __float2bfloat16(y);
    return *(uint32_t*)&v;
}
__device__ __forceinline__ uint32_t pack_lo(float x, float y) {
    __nv_bfloat16 hx = __float2bfloat16(x);
    __nv_bfloat16 hy = __float2bfloat16(y);
    __nv_bfloat162 v;
    v.x = __float2bfloat16(x - __bfloat162float(hx));
    v.y = __float2bfloat16(y - __bfloat162float(hy));
    return *(uint32_t*)&v;
}

// ===========================================================================
// Kernel 1: tensor-core projections via mma.sync bf16x3 split (fused convert)
//   C ≈ Ah·Wh + Al·Wh + Ah·Wl  (fp32 accumulate; dropped Al·Wl ~ 4e-6)
// CTA: 128x64 tile, BK=32, 256 threads (8 warps 4x2, warp tile 32x32).
// B staged in natural [k][n] layout (packed 4B stores), read via ldmatrix.trans.
// Smem stride 72 (144B): conflict-free ldmatrix for both A and B.
// ===========================================================================
__global__ __launch_bounds__(256) void proj_mma_kernel(
    const float* __restrict__ Aq, const float* __restrict__ Ak,
    const float* __restrict__ Wq, const float* __restrict__ Wk,
    const int* __restrict__ valid_lens)
{
    constexpr int BM = 128, BN = 64, BK = 32, SP = 72;   // padded stride
    __shared__ __nv_bfloat16 sAh[BM][SP], sAl[BM][SP];   // [m][k]
    __shared__ __nv_bfloat16 sBh[BK][SP], sBl[BK][SP];   // [k][n] natural

    const int z  = blockIdx.z;            // 0: q-proj, 1: k-proj
    const int m0 = blockIdx.x * BM;
    const int n0 = blockIdx.y * BN;

    // k-projection rows beyond valid_len are never read by score_kernel
    if (z) {
        const int b = m0 >> 8;
        if ((m0 & 255) >= __ldg(&valid_lens[b])) return;
    }

    const float* A = z ? Ak : Aq;
    const float* W = z ? Wk : Wq;
    float*       C = z ? g_k : g_q;

    const int t    = threadIdx.x;
    const int lane = t & 31;
    const int warp = t >> 5;
    const int wm   = (warp & 3) * 32;     // warp m offset
    const int wn   = (warp >> 2) * 32;    // warp n offset

    float acc[2][4][4] = {};              // [mt][nt][frag]

    for (int k0 = 0; k0 < H; k0 += BK) {
        // --- stage A (128 x 32 fp32 -> hi/lo bf16): 1024 float4, 4/thread ---
        #pragma unroll
        for (int i = 0; i < 4; i++) {
            const int idx = t + i * 256;
            const int r   = idx >> 3;          // 8 float4 per row
            const int c   = (idx & 7) << 2;
            float4 v = *(const float4*)&A[(m0 + r) * H + k0 + c];
            *(uint32_t*)&sAh[r][c]     = pack_hi(v.x, v.y);
            *(uint32_t*)&sAh[r][c + 2] = pack_hi(v.z, v.w);
            *(uint32_t*)&sAl[r][c]     = pack_lo(v.x, v.y);
            *(uint32_t*)&sAl[r][c + 2] = pack_lo(v.z, v.w);
        }
        // --- stage B natural [k][n]: 512 float4, 2/thread, packed stores ---
        #pragma unroll
        for (int i = 0; i < 2; i++) {
            const int idx = t + i * 256;
            const int kr  = idx >> 4;          // 16 float4 per W row
            const int nc  = (idx & 15) << 2;
            float4 v = *(const float4*)&W[(k0 + kr) * H + n0 + nc];
            *(uint32_t*)&sBh[kr][nc]     = pack_hi(v.x, v.y);
            *(uint32_t*)&sBh[kr][nc + 2] = pack_hi(v.z, v.w);
            *(uint32_t*)&sBl[kr][nc]     = pack_lo(v.x, v.y);
            *(uint32_t*)&sBl[kr][nc + 2] = pack_lo(v.z, v.w);
        }
        __syncthreads();

        #pragma unroll
        for (int ks = 0; ks < 2; ks++) {
            const int kb = ks * 16;

            uint32_t ah[2][4], al[2][4];
            #pragma unroll
            for (int mt = 0; mt < 2; mt++) {
                const int row = wm + mt * 16 + (lane & 15);
                const int kc  = kb + ((lane >> 4) << 3);
                ldsm_x4(ah[mt], smem_u32(&sAh[row][kc]));
                ldsm_x4(al[mt], smem_u32(&sAl[row][kc]));
            }
            #pragma unroll
            for (int nt = 0; nt < 4; nt++) {
                uint32_t bh[2], bl[2];
                const int krow  = kb + (lane & 15);     // lanes 0-15 -> 16 k-rows
                const int nbase = wn + nt * 8;
                ldsm_x2_trans(bh, smem_u32(&sBh[krow][nbase]));
                ldsm_x2_trans(bl, smem_u32(&sBl[krow][nbase]));
                #pragma unroll
                for (int mt = 0; mt < 2; mt++) {
                    mma_bf16(acc[mt][nt], ah[mt], bh);
                    mma_bf16(acc[mt][nt], al[mt], bh);
                    mma_bf16(acc[mt][nt], ah[mt], bl);
                }
            }
        }
        __syncthreads();
    }

    // --- epilogue: fragment -> gmem ---
    #pragma unroll
    for (int mt = 0; mt < 2; mt++) {
        const int r0 = m0 + wm + mt * 16 + (lane >> 2);
        #pragma unroll
        for (int nt = 0; nt < 4; nt++) {
            const int c0 = n0 + wn + nt * 8 + (lane & 3) * 2;
            *(float2*)&C[r0 * H + c0]       = make_float2(acc[mt][nt][0], acc[mt][nt][1]);
            *(float2*)&C[(r0 + 8) * H + c0] = make_float2(acc[mt][nt][2], acc[mt][nt][3]);
        }
    }
}

// ---------------------------------------------------------------------------
// Kernel 2: scores[b, q0:q0+16, j0:j0+32] = sum_h w[h]*tanh(q+k)
// One CTA per (j-tile, b, q-tile); CTAs beyond valid_len exit instantly.
// ---------------------------------------------------------------------------
__global__ __launch_bounds__(128, 4) void score_kernel(
    const int* __restrict__ valid_lens, const float* __restrict__ w_v)
{
    constexpr int QI = 16;
    constexpr int KJ = 32;
    constexpr int HP = H + 4;

    const int jt = blockIdx.x;
    const int b  = blockIdx.y;
    const int q0 = blockIdx.z * QI;
    const int j0 = jt * KJ;

    const int vl = __ldg(&valid_lens[b]);
    if (j0 >= vl) return;

    extern __shared__ float sm[];
    float* sq = sm;             // QI * HP
    float* sk = sq + QI * HP;   // KJ * HP
    float* sw = sk + KJ * HP;   // H

    const int t    = threadIdx.x;
    const int lane = t & 31;
    const int warp = t >> 5;

    for (int idx = t; idx < QI * (H / 4); idx += 128) {
        const int i  = idx >> 6;
        const int hc = (idx & 63) << 2;
        *(float4*)&sq[i * HP + hc] =
            *(const float4*)&g_q[(b * LQ + q0 + i) * H + hc];
    }
    for (int idx = t; idx < KJ * (H / 4); idx += 128) {
        const int j  = idx >> 6;
        const int hc = (idx & 63) << 2;
        *(float4*)&sk[j * HP + hc] =
            *(const float4*)&g_k[(b * LK + j0 + j) * H + hc];
    }
    if (t < H / 4) *(float4*)&sw[t * 4] = *(const float4*)&w_v[t * 4];
    __syncthreads();

    float a0 = 0.f, a1 = 0.f, a2 = 0.f, a3 = 0.f;
    const float* qp0 = &sq[(warp * 4 + 0) * HP];
    const float* qp1 = &sq[(warp * 4 + 1) * HP];
    const float* qp2 = &sq[(warp * 4 + 2) * HP];
    const float* qp3 = &sq[(warp * 4 + 3) * HP];
    const float* kp  = &sk[lane * HP];

    #pragma unroll 2
    for (int h = 0; h < H; h += 4) {
        float4 k4 = *(const float4*)&kp[h];
        float4 w4 = *(const float4*)&sw[h];
        float4 q0v = *(const float4*)&qp0[h];
        float4 q1v = *(const float4*)&qp1[h];
        float4 q2v = *(const float4*)&qp2[h];
        float4 q3v = *(const float4*)&qp3[h];

        a0 += w4.x * tanha(q0v.x + k4.x);
        a0 += w4.y * tanha(q0v.y + k4.y);
        a0 += w4.z * tanha(q0v.z + k4.z);
        a0 += w4.w * tanha(q0v.w + k4.w);

        a1 += w4.x * tanha(q1v.x + k4.x);
        a1 += w4.y * tanha(q1v.y + k4.y);
        a1 += w4.z * tanha(q1v.z + k4.z);
        a1 += w4.w * tanha(q1v.w + k4.w);

        a2 += w4.x * tanha(q2v.x + k4.x);
        a2 += w4.y * tanha(q2v.y + k4.y);
        a2 += w4.z * tanha(q2v.z + k4.z);
        a2 += w4.w * tanha(q2v.w + k4.w);

        a3 += w4.x * tanha(q3v.x + k4.x);
        a3 += w4.y * tanha(q3v.y + k4.y);
        a3 += w4.z * tanha(q3v.z + k4.z);
        a3 += w4.w * tanha(q3v.w + k4.w);
    }

    const int rbase = b * LQ + q0 + warp * 4;
    g_s[(rbase + 0) * LK + j0 + lane] = a0;
    g_s[(rbase + 1) * LK + j0 + lane] = a1;
    g_s[(rbase + 2) * LK + j0 + lane] = a2;
    g_s[(rbase + 3) * LK + j0 + lane] = a3;
}

// ---------------------------------------------------------------------------
// Kernel 3: masked softmax over j + out = P @ V
// Stages only columns j < valid_len; exp pass zeroes the rest of smem.
// ---------------------------------------------------------------------------
__global__ __launch_bounds__(128) void softpv_kernel(
    const float* __restrict__ values, const int* __restrict__ valid_lens,
    float* __restrict__ out)
{
    constexpr int QI = 8;
    __shared__ float sp[QI * LK];

    const int b    = blockIdx.x;
    const int q0   = blockIdx.y * QI;
    const int t    = threadIdx.x;
    const int lane = t & 31;
    const int warp = t >> 5;

    const int vl = valid_lens[b];

    for (int idx = t; idx < QI * (LK / 4); idx += 128) {
        const int i  = idx >> 6;
        const int jc = (idx & 63) << 2;
        if (jc < vl)
            *(float4*)&sp[i * LK + jc] =
                *(const float4*)&g_s[(b * LQ + q0 + i) * LK + jc];
    }
    __syncthreads();

    #pragma unroll
    for (int rr = 0; rr < 2; rr++) {
        const int r = warp + rr * 4;
        float* row = &sp[r * LK];

        float m = -1e30f;
        for (int j = lane; j < LK; j += 32) {
            float s = (j < vl) ? row[j] : -1e30f;
            m = fmaxf(m, s);
        }
        #pragma unroll
        for (int o = 16; o; o >>= 1) m = fmaxf(m, __shfl_xor_sync(0xffffffffu, m, o));

        float ssum = 0.f;
        for (int j = lane; j < LK; j += 32) {
            float e = (j < vl) ? __expf(row[j] - m) : 0.f;
            row[j] = e;
            ssum += e;
        }
        #pragma unroll
        for (int o = 16; o; o >>= 1) ssum += __shfl_xor_sync(0xffffffffu, ssum, o);

        const float inv = 1.0f / ssum;
        for (int j = lane; j < LK; j += 32) row[j] *= inv;
    }
    __syncthreads();

    const int ig = (t >> 6) * 4;        // 0 or 4
    const int v0 = (t & 63) * 4;        // 0..252
    float acc[4][4] = {};
    const float* vb = &values[b * LK * H];

    const int jend = min(LK, (vl + 3) & ~3);
    for (int j = 0; j < jend; j += 4) {
        float vvf[4][4];
        #pragma unroll
        for (int jj = 0; jj < 4; jj++) {
            float4 tmp = *(const float4*)&vb[(j + jj) * H + v0];
            vvf[jj][0] = tmp.x; vvf[jj][1] = tmp.y; vvf[jj][2] = tmp.z; vvf[jj][3] = tmp.w;
        }
        #pragma unroll
        for (int r = 0; r < 4; r++) {
            float4 p = *(const float4*)&sp[(ig + r) * LK + j];
            #pragma unroll
            for (int c = 0; c < 4; c++) {
                acc[r][c] += p.x * vvf[0][c];
                acc[r][c] += p.y * vvf[1][c];
                acc[r][c] += p.z * vvf[2][c];
                acc[r][c] += p.w * vvf[3][c];
            }
        }
    }

    #pragma unroll
    for (int r = 0; r < 4; r++) {
        float4 o = make_float4(acc[r][0], acc[r][1], acc[r][2], acc[r][3]);
        *(float4*)&out[(b * LQ + q0 + ig + r) * H + v0] = o;
    }
}

// ---------------------------------------------------------------------------
extern "C" void kernel_launch(void* const* d_in, const int* in_sizes, int n_in,
                              void* d_out, int out_size) {
    (void)in_sizes; (void)n_in; (void)out_size;
    const float* queries = (const float*)d_in[0];
    const float* keys    = (const float*)d_in[1];
    const float* values  = (const float*)d_in[2];
    const int*   vlens   = (const int*)d_in[3];
    const float* Wq      = (const float*)d_in[4];
    const float* Wk      = (const float*)d_in[5];
    const float* wv      = (const float*)d_in[6];
    float* out = (float*)d_out;

    dim3 pg((NB * LQ) / 128, H / 64, 2);   // 32 x 4 x 2 = 256 CTAs
    proj_mma_kernel<<<pg, 256>>>(queries, keys, Wq, Wk, vlens);

    constexpr int QI = 16, KJ = 32, HP = H + 4;
    constexpr int SMEM = (QI * HP + KJ * HP + H) * (int)sizeof(float);
    cudaFuncSetAttribute(score_kernel, cudaFuncAttributeMaxDynamicSharedMemorySize, SMEM);
    dim3 sg(LK / KJ, NB, LQ / QI);   // j-tile fastest
    score_kernel<<<sg, 128, SMEM>>>(vlens, wv);

    dim3 og(NB, LQ / 8);
    softpv_kernel<<<og, 128>>>(values, vlens, out);
}

// round 11
// speedup vs baseline: 1.1467x; 1.0208x over previous
#include <cuda_runtime.h>
#include <cuda_bf16.h>
#include <cstdint>

// Problem constants
constexpr int NB  = 16;    // batch
constexpr int LQ  = 256;
constexpr int LK  = 256;
constexpr int H   = 256;   // hidden = DQ = DK = DV

// Scratch (no cudaMalloc allowed)
__device__ float g_q[NB * LQ * H];
__device__ float g_k[NB * LK * H];
__device__ float g_s[NB * LQ * LK];   // raw scores

__device__ __forceinline__ float tanha(float x) {
    float r;
    asm("tanh.approx.f32 %0, %1;" : "=f"(r) : "f"(x));
    return r;
}

__device__ __forceinline__ uint32_t smem_u32(const void* p) {
    uint32_t a;
    asm("{ .reg .u64 t; cvta.to.shared.u64 t, %1; cvt.u32.u64 %0, t; }"
        : "=r"(a) : "l"(p));
    return a;
}

__device__ __forceinline__ void ldsm_x4(uint32_t* r, uint32_t addr) {
    asm volatile("ldmatrix.sync.aligned.m8n8.x4.shared.b16 {%0,%1,%2,%3}, [%4];"
        : "=r"(r[0]), "=r"(r[1]), "=r"(r[2]), "=r"(r[3]) : "r"(addr));
}
__device__ __forceinline__ void ldsm_x2_trans(uint32_t* r, uint32_t addr) {
    asm volatile("ldmatrix.sync.aligned.m8n8.x2.trans.shared.b16 {%0,%1}, [%2];"
        : "=r"(r[0]), "=r"(r[1]) : "r"(addr));
}
__device__ __forceinline__ void mma_bf16(float* c, const uint32_t* a, const uint32_t* b) {
    asm volatile(
        "mma.sync.aligned.m16n8k16.row.col.f32.bf16.bf16.f32 "
        "{%0,%1,%2,%3}, {%4,%5,%6,%7}, {%8,%9}, {%0,%1,%2,%3};"
        : "+f"(c[0]), "+f"(c[1]), "+f"(c[2]), "+f"(c[3])
        : "r"(a[0]), "r"(a[1]), "r"(a[2]), "r"(a[3]), "r"(b[0]), "r"(b[1]));
}

__device__ __forceinline__ uint32_t pack_hi(float x, float y) {
    __nv_bfloat162 v;
    v.x = __float2bfloat16(x);
    v.y = __float2bfloat16(y);
    return *(uint32_t*)&v;
}
__device__ __forceinline__ uint32_t pack_lo(float x, float y) {
    __nv_bfloat16 hx = __float2bfloat16(x);
    __nv_bfloat16 hy = __float2bfloat16(y);
    __nv_bfloat162 v;
    v.x = __float2bfloat16(x - __bfloat162float(hx));
    v.y = __float2bfloat16(y - __bfloat162float(hy));
    return *(uint32_t*)&v;
}

// ===========================================================================
// Kernel 1: tensor-core projections via mma.sync bf16x3 split (fused convert)
//   C ≈ Ah·Wh + Al·Wh + Ah·Wl  (fp32 accumulate; dropped Al·Wl ~ 4e-6)
// CTA: 128x128 tile, BK=32, 512 threads (16 warps 4x4, warp tile 32x32).
// grid = 128 CTAs -> SINGLE WAVE on 148 SMs.
// B staged natural [k][n] (packed 4B stores), read via ldmatrix.trans.
// Strides: A 72 (144B), B 136 (272B) -> both conflict-free for ldmatrix.
// ===========================================================================
constexpr int PROJ_BM = 128, PROJ_BN = 128, PROJ_BK = 32;
constexpr int SP_A = 72, SP_B = 136;
constexpr int SM_AH_OFF = 0;
constexpr int SM_AL_OFF = SM_AH_OFF + PROJ_BM * SP_A;              // bf16 elems
constexpr int SM_BH_OFF = SM_AL_OFF + PROJ_BM * SP_A;
constexpr int SM_BL_OFF = SM_BH_OFF + PROJ_BK * SP_B;
constexpr int PROJ_SMEM_BYTES = (SM_BL_OFF + PROJ_BK * SP_B) * 2;  // 54272

__global__ __launch_bounds__(512) void proj_mma_kernel(
    const float* __restrict__ Aq, const float* __restrict__ Ak,
    const float* __restrict__ Wq, const float* __restrict__ Wk,
    const int* __restrict__ valid_lens)
{
    extern __shared__ __nv_bfloat16 smp[];
    __nv_bfloat16* sAh = smp + SM_AH_OFF;   // [128][72]
    __nv_bfloat16* sAl = smp + SM_AL_OFF;
    __nv_bfloat16* sBh = smp + SM_BH_OFF;   // [32][136]
    __nv_bfloat16* sBl = smp + SM_BL_OFF;

    const int z  = blockIdx.z;            // 0: q-proj, 1: k-proj
    const int m0 = blockIdx.x * PROJ_BM;
    const int n0 = blockIdx.y * PROJ_BN;

    // k-projection rows beyond valid_len are never read by score_kernel
    if (z) {
        const int b = m0 >> 8;
        if ((m0 & 255) >= __ldg(&valid_lens[b])) return;
    }

    const float* A = z ? Ak : Aq;
    const float* W = z ? Wk : Wq;
    float*       C = z ? g_k : g_q;

    const int t    = threadIdx.x;
    const int lane = t & 31;
    const int warp = t >> 5;
    const int wm   = (warp & 3) * 32;     // 4 warps cover 128 m
    const int wn   = (warp >> 2) * 32;    // 4 warps cover 128 n

    float acc[2][4][4] = {};              // [mt][nt][frag]

    for (int k0 = 0; k0 < H; k0 += PROJ_BK) {
        // --- stage A (128 x 32 fp32 -> hi/lo bf16): 1024 float4, 2/thread ---
        #pragma unroll
        for (int i = 0; i < 2; i++) {
            const int idx = t + i * 512;
            const int r   = idx >> 3;          // 8 float4 per row
            const int c   = (idx & 7) << 2;
            float4 v = *(const float4*)&A[(m0 + r) * H + k0 + c];
            *(uint32_t*)&sAh[r * SP_A + c]     = pack_hi(v.x, v.y);
            *(uint32_t*)&sAh[r * SP_A + c + 2] = pack_hi(v.z, v.w);
            *(uint32_t*)&sAl[r * SP_A + c]     = pack_lo(v.x, v.y);
            *(uint32_t*)&sAl[r * SP_A + c + 2] = pack_lo(v.z, v.w);
        }
        // --- stage B natural [k][n] (32 x 128): 1024 float4, 2/thread ---
        #pragma unroll
        for (int i = 0; i < 2; i++) {
            const int idx = t + i * 512;
            const int kr  = idx >> 5;          // 32 float4 per W row
            const int nc  = (idx & 31) << 2;
            float4 v = *(const float4*)&W[(k0 + kr) * H + n0 + nc];
            *(uint32_t*)&sBh[kr * SP_B + nc]     = pack_hi(v.x, v.y);
            *(uint32_t*)&sBh[kr * SP_B + nc + 2] = pack_hi(v.z, v.w);
            *(uint32_t*)&sBl[kr * SP_B + nc]     = pack_lo(v.x, v.y);
            *(uint32_t*)&sBl[kr * SP_B + nc + 2] = pack_lo(v.z, v.w);
        }
        __syncthreads();

        #pragma unroll
        for (int ks = 0; ks < 2; ks++) {
            const int kb = ks * 16;

            uint32_t ah[2][4], al[2][4];
            #pragma unroll
            for (int mt = 0; mt < 2; mt++) {
                const int row = wm + mt * 16 + (lane & 15);
                const int kc  = kb + ((lane >> 4) << 3);
                ldsm_x4(ah[mt], smem_u32(&sAh[row * SP_A + kc]));
                ldsm_x4(al[mt], smem_u32(&sAl[row * SP_A + kc]));
            }
            #pragma unroll
            for (int nt = 0; nt < 4; nt++) {
                uint32_t bh[2], bl[2];
                const int krow  = kb + (lane & 15);
                const int nbase = wn + nt * 8;
                ldsm_x2_trans(bh, smem_u32(&sBh[krow * SP_B + nbase]));
                ldsm_x2_trans(bl, smem_u32(&sBl[krow * SP_B + nbase]));
                #pragma unroll
                for (int mt = 0; mt < 2; mt++) {
                    mma_bf16(acc[mt][nt], ah[mt], bh);
                    mma_bf16(acc[mt][nt], al[mt], bh);
                    mma_bf16(acc[mt][nt], ah[mt], bl);
                }
            }
        }
        __syncthreads();
    }

    // --- epilogue: fragment -> gmem ---
    #pragma unroll
    for (int mt = 0; mt < 2; mt++) {
        const int r0 = m0 + wm + mt * 16 + (lane >> 2);
        #pragma unroll
        for (int nt = 0; nt < 4; nt++) {
            const int c0 = n0 + wn + nt * 8 + (lane & 3) * 2;
            *(float2*)&C[r0 * H + c0]       = make_float2(acc[mt][nt][0], acc[mt][nt][1]);
            *(float2*)&C[(r0 + 8) * H + c0] = make_float2(acc[mt][nt][2], acc[mt][nt][3]);
        }
    }
}

// ---------------------------------------------------------------------------
// Kernel 2: scores[b, q0:q0+16, j0:j0+32] = sum_h w[h]*tanh(q+k)
// One CTA per (j-tile, b, q-tile); CTAs beyond valid_len exit instantly.
// ---------------------------------------------------------------------------
__global__ __launch_bounds__(128, 4) void score_kernel(
    const int* __restrict__ valid_lens, const float* __restrict__ w_v)
{
    constexpr int QI = 16;
    constexpr int KJ = 32;
    constexpr int HP = H + 4;

    const int jt = blockIdx.x;
    const int b  = blockIdx.y;
    const int q0 = blockIdx.z * QI;
    const int j0 = jt * KJ;

    const int vl = __ldg(&valid_lens[b]);
    if (j0 >= vl) return;

    extern __shared__ float sm[];
    float* sq = sm;             // QI * HP
    float* sk = sq + QI * HP;   // KJ * HP
    float* sw = sk + KJ * HP;   // H

    const int t    = threadIdx.x;
    const int lane = t & 31;
    const int warp = t >> 5;

    for (int idx = t; idx < QI * (H / 4); idx += 128) {
        const int i  = idx >> 6;
        const int hc = (idx & 63) << 2;
        *(float4*)&sq[i * HP + hc] =
            *(const float4*)&g_q[(b * LQ + q0 + i) * H + hc];
    }
    for (int idx = t; idx < KJ * (H / 4); idx += 128) {
        const int j  = idx >> 6;
        const int hc = (idx & 63) << 2;
        *(float4*)&sk[j * HP + hc] =
            *(const float4*)&g_k[(b * LK + j0 + j) * H + hc];
    }
    if (t < H / 4) *(float4*)&sw[t * 4] = *(const float4*)&w_v[t * 4];
    __syncthreads();

    float a0 = 0.f, a1 = 0.f, a2 = 0.f, a3 = 0.f;
    const float* qp0 = &sq[(warp * 4 + 0) * HP];
    const float* qp1 = &sq[(warp * 4 + 1) * HP];
    const float* qp2 = &sq[(warp * 4 + 2) * HP];
    const float* qp3 = &sq[(warp * 4 + 3) * HP];
    const float* kp  = &sk[lane * HP];

    #pragma unroll 2
    for (int h = 0; h < H; h += 4) {
        float4 k4 = *(const float4*)&kp[h];
        float4 w4 = *(const float4*)&sw[h];
        float4 q0v = *(const float4*)&qp0[h];
        float4 q1v = *(const float4*)&qp1[h];
        float4 q2v = *(const float4*)&qp2[h];
        float4 q3v = *(const float4*)&qp3[h];

        a0 += w4.x * tanha(q0v.x + k4.x);
        a0 += w4.y * tanha(q0v.y + k4.y);
        a0 += w4.z * tanha(q0v.z + k4.z);
        a0 += w4.w * tanha(q0v.w + k4.w);

        a1 += w4.x * tanha(q1v.x + k4.x);
        a1 += w4.y * tanha(q1v.y + k4.y);
        a1 += w4.z * tanha(q1v.z + k4.z);
        a1 += w4.w * tanha(q1v.w + k4.w);

        a2 += w4.x * tanha(q2v.x + k4.x);
        a2 += w4.y * tanha(q2v.y + k4.y);
        a2 += w4.z * tanha(q2v.z + k4.z);
        a2 += w4.w * tanha(q2v.w + k4.w);

        a3 += w4.x * tanha(q3v.x + k4.x);
        a3 += w4.y * tanha(q3v.y + k4.y);
        a3 += w4.z * tanha(q3v.z + k4.z);
        a3 += w4.w * tanha(q3v.w + k4.w);
    }

    const int rbase = b * LQ + q0 + warp * 4;
    g_s[(rbase + 0) * LK + j0 + lane] = a0;
    g_s[(rbase + 1) * LK + j0 + lane] = a1;
    g_s[(rbase + 2) * LK + j0 + lane] = a2;
    g_s[(rbase + 3) * LK + j0 + lane] = a3;
}

// ---------------------------------------------------------------------------
// Kernel 3: masked softmax over j + out = P @ V
// Stages only columns j < valid_len; exp pass zeroes the rest of smem.
// ---------------------------------------------------------------------------
__global__ __launch_bounds__(128) void softpv_kernel(
    const float* __restrict__ values, const int* __restrict__ valid_lens,
    float* __restrict__ out)
{
    constexpr int QI = 8;
    __shared__ float sp[QI * LK];

    const int b    = blockIdx.x;
    const int q0   = blockIdx.y * QI;
    const int t    = threadIdx.x;
    const int lane = t & 31;
    const int warp = t >> 5;

    const int vl = valid_lens[b];

    for (int idx = t; idx < QI * (LK / 4); idx += 128) {
        const int i  = idx >> 6;
        const int jc = (idx & 63) << 2;
        if (jc < vl)
            *(float4*)&sp[i * LK + jc] =
                *(const float4*)&g_s[(b * LQ + q0 + i) * LK + jc];
    }
    __syncthreads();

    #pragma unroll
    for (int rr = 0; rr < 2; rr++) {
        const int r = warp + rr * 4;
        float* row = &sp[r * LK];

        float m = -1e30f;
        for (int j = lane; j < LK; j += 32) {
            float s = (j < vl) ? row[j] : -1e30f;
            m = fmaxf(m, s);
        }
        #pragma unroll
        for (int o = 16; o; o >>= 1) m = fmaxf(m, __shfl_xor_sync(0xffffffffu, m, o));

        float ssum = 0.f;
        for (int j = lane; j < LK; j += 32) {
            float e = (j < vl) ? __expf(row[j] - m) : 0.f;
            row[j] = e;
            ssum += e;
        }
        #pragma unroll
        for (int o = 16; o; o >>= 1) ssum += __shfl_xor_sync(0xffffffffu, ssum, o);

        const float inv = 1.0f / ssum;
        for (int j = lane; j < LK; j += 32) row[j] *= inv;
    }
    __syncthreads();

    const int ig = (t >> 6) * 4;        // 0 or 4
    const int v0 = (t & 63) * 4;        // 0..252
    float acc[4][4] = {};
    const float* vb = &values[b * LK * H];

    const int jend = min(LK, (vl + 3) & ~3);
    for (int j = 0; j < jend; j += 4) {
        float vvf[4][4];
        #pragma unroll
        for (int jj = 0; jj < 4; jj++) {
            float4 tmp = *(const float4*)&vb[(j + jj) * H + v0];
            vvf[jj][0] = tmp.x; vvf[jj][1] = tmp.y; vvf[jj][2] = tmp.z; vvf[jj][3] = tmp.w;
        }
        #pragma unroll
        for (int r = 0; r < 4; r++) {
            float4 p = *(const float4*)&sp[(ig + r) * LK + j];
            #pragma unroll
            for (int c = 0; c < 4; c++) {
                acc[r][c] += p.x * vvf[0][c];
                acc[r][c] += p.y * vvf[1][c];
                acc[r][c] += p.z * vvf[2][c];
                acc[r][c] += p.w * vvf[3][c];
            }
        }
    }

    #pragma unroll
    for (int r = 0; r < 4; r++) {
        float4 o = make_float4(acc[r][0], acc[r][1], acc[r][2], acc[r][3]);
        *(float4*)&out[(b * LQ + q0 + ig + r) * H + v0] = o;
    }
}

// ---------------------------------------------------------------------------
extern "C" void kernel_launch(void* const* d_in, const int* in_sizes, int n_in,
                              void* d_out, int out_size) {
    (void)in_sizes; (void)n_in; (void)out_size;
    const float* queries = (const float*)d_in[0];
    const float* keys    = (const float*)d_in[1];
    const float* values  = (const float*)d_in[2];
    const int*   vlens   = (const int*)d_in[3];
    const float* Wq      = (const float*)d_in[4];
    const float* Wk      = (const float*)d_in[5];
    const float* wv      = (const float*)d_in[6];
    float* out = (float*)d_out;

    cudaFuncSetAttribute(proj_mma_kernel,
                         cudaFuncAttributeMaxDynamicSharedMemorySize, PROJ_SMEM_BYTES);
    dim3 pg((NB * LQ) / PROJ_BM, H / PROJ_BN, 2);   // 32 x 2 x 2 = 128 CTAs
    proj_mma_kernel<<<pg, 512, PROJ_SMEM_BYTES>>>(queries, keys, Wq, Wk, vlens);

    constexpr int QI = 16, KJ = 32, HP = H + 4;
    constexpr int SMEM = (QI * HP + KJ * HP + H) * (int)sizeof(float);
    cudaFuncSetAttribute(score_kernel, cudaFuncAttributeMaxDynamicSharedMemorySize, SMEM);
    dim3 sg(LK / KJ, NB, LQ / QI);   // j-tile fastest
    score_kernel<<<sg, 128, SMEM>>>(vlens, wv);

    dim3 og(NB, LQ / 8);
    softpv_kernel<<<og, 128>>>(values, vlens, out);
}